// round 5
// baseline (speedup 1.0000x reference)
#include <cuda_runtime.h>
#include <cuda_fp16.h>
#include <cstdint>
#include <cstddef>

#define NE 8192
#define NF 64
#define NH 256
#define NN (128*8192)
#define NTILES 8192
#define NTHREADS 256

// smem byte offsets (all swizzled f16)
#define OFF_SA   0u        // A tile [128][128k] f16, row stride 256B
#define OFF_SH   32768u    // h tile [128][256k] f16, row stride 512B
#define OFF_SW1  98304u    // W1^T  [256n][128k] f16, row stride 256B
#define OFF_SW2  163840u   // W2^T  [128n][256k] f16, row stride 512B
#define OFF_SB1  229376u
#define OFF_SB2  230400u
#define SMEM_REQ 230912

__device__ __forceinline__ uint32_t smem_u32(const void* p){
    uint32_t a;
    asm("{ .reg .u64 t; cvta.to.shared.u64 t, %1; cvt.u32.u64 %0, t; }" : "=r"(a) : "l"(p));
    return a;
}
__device__ __forceinline__ uint32_t pack_h2(float a, float b){
    __half2 h = __floats2half2_rn(a, b);
    return *reinterpret_cast<uint32_t*>(&h);
}
__device__ __forceinline__ void ldmx4(uint32_t& a0, uint32_t& a1, uint32_t& a2, uint32_t& a3, uint32_t addr){
    asm volatile("ldmatrix.sync.aligned.m8n8.x4.shared.b16 {%0,%1,%2,%3}, [%4];"
                 : "=r"(a0), "=r"(a1), "=r"(a2), "=r"(a3) : "r"(addr));
}
__device__ __forceinline__ void sts32(uint32_t addr, uint32_t v){
    asm volatile("st.shared.b32 [%0], %1;" :: "r"(addr), "r"(v) : "memory");
}
__device__ __forceinline__ void sts128(uint32_t addr, uint32_t p0, uint32_t p1, uint32_t p2, uint32_t p3){
    asm volatile("st.shared.v4.b32 [%0], {%1,%2,%3,%4};" :: "r"(addr), "r"(p0), "r"(p1), "r"(p2), "r"(p3) : "memory");
}
__device__ __forceinline__ void mma16(float c[4], uint32_t a0, uint32_t a1, uint32_t a2, uint32_t a3,
                                      uint32_t b0, uint32_t b1){
    asm volatile(
        "mma.sync.aligned.m16n8k16.row.col.f32.f16.f16.f32 "
        "{%0,%1,%2,%3},{%4,%5,%6,%7},{%8,%9},{%0,%1,%2,%3};\n"
        : "+f"(c[0]), "+f"(c[1]), "+f"(c[2]), "+f"(c[3])
        : "r"(a0), "r"(a1), "r"(a2), "r"(a3), "r"(b0), "r"(b1));
}

__global__ void __launch_bounds__(NTHREADS, 1)
fused_h16c(const float* __restrict__ x,  const float* __restrict__ gf,
           const float* __restrict__ W1, const float* __restrict__ b1g,
           const float* __restrict__ W2, const float* __restrict__ b2g,
           const int*   __restrict__ pidx, float* __restrict__ out, int write_event)
{
    extern __shared__ char sm[];
    const int tid  = threadIdx.x;
    const int warp = tid >> 5, lane = tid & 31;
    const int grp = lane >> 2, tig = lane & 3;
    const int wm = warp >> 2, wn = warp & 3;   // 2 x 4 warp grid

    const uint32_t smu = smem_u32(sm);
    const uint32_t sAu = smu + OFF_SA;
    const uint32_t sHu = smu + OFF_SH;
    float* sb1 = (float*)(sm + OFF_SB1);
    float* sb2 = (float*)(sm + OFF_SB2);

    // ---- one-time weight preload (swizzled f16) ----
    for (int i = tid; i < 128 * NH; i += NTHREADS) {
        int k = i >> 8, n = i & 255;
        uint32_t cb = (uint32_t)(2 * k);
        uint32_t off = (uint32_t)n * 256u + ((cb & ~15u) ^ (((uint32_t)n & 7u) << 4)) + (cb & 15u);
        *(half*)(sm + OFF_SW1 + off) = __float2half_rn(W1[i]);
    }
    for (int i = tid; i < NH * 128; i += NTHREADS) {
        int k = i >> 7, n = i & 127;
        uint32_t cb = (uint32_t)(2 * k);
        uint32_t off = (uint32_t)n * 512u + ((cb & ~15u) ^ (((uint32_t)n & 7u) << 4)) + (cb & 15u);
        *(half*)(sm + OFF_SW2 + off) = __float2half_rn(W2[i]);
    }
    sb1[tid] = b1g[tid];
    if (tid < 128) sb2[tid] = b2g[tid];
    __syncthreads();

    // per-thread constants
    const uint32_t amask = ((uint32_t)(lane & 7)) << 4;   // A ldmatrix swizzle
    const uint32_t ahi   = ((uint32_t)(lane >> 4)) << 4;  // A k-half select
    const int lr = lane & 15;

    // B ldmatrix lane mapping: rowSel = 8*(lane>=16) + (lane&7); k-hi half for lanes 8-15,24-31
    const uint32_t browSel = (uint32_t)(((lane & 16) >> 1) + (lane & 7));
    const uint32_t bq      = (uint32_t)((lane & 8) << 1);          // 0 or 16
    const uint32_t bmsk    = ((uint32_t)(lane & 7)) << 4;

    const int nb1 = wn * 64;
    const int nb2 = wn * 32;
    const uint32_t b1Ldsm = smu + OFF_SW1 + ((uint32_t)nb1 + browSel) * 256u;
    const uint32_t b2Ldsm = smu + OFF_SW2 + ((uint32_t)nb2 + browSel) * 512u;

    uint32_t a1Base[4], a2Base[4];
    #pragma unroll
    for (int mf = 0; mf < 4; mf++) {
        a1Base[mf] = sAu + (uint32_t)(64*wm + 16*mf + lr) * 256u;
        a2Base[mf] = sHu + (uint32_t)(64*wm + 16*mf + lr) * 512u;
    }

    // gather assignment: 2 threads per row
    const int gr = tid >> 1, gq = tid & 1;
    int pi_cur = pidx[(blockIdx.x << 7) + gr];

    // ================= persistent tile loop =================
    for (int t = blockIdx.x; t < NTILES; t += gridDim.x) {
        const int m0 = t << 7;

        // ---- Phase A: gather A (swizzled f16) + identity copy + event ----
        {
            const uint32_t rb  = sAu + (uint32_t)gr * 256u;
            const uint32_t msk = ((uint32_t)(gr & 7)) << 4;
            const float4* src = gq ? (const float4*)(gf + (size_t)(((unsigned)pi_cur) & (NE-1)) * NF)
                                   : (const float4*)(x  + (size_t)pi_cur * NF);
            const uint32_t cbase = gq ? 128u : 0u;
            float4 g[16];
            #pragma unroll
            for (int c = 0; c < 16; c++) g[c] = src[c];

            // identity copy (independent LDGs, transient regs)
            uint4 cpv[8];
            const uint4* xs = (const uint4*)x + (size_t)t * 2048;
            uint4*       od = (uint4*)out     + (size_t)t * 2048;
            #pragma unroll
            for (int j = 0; j < 8; j++) cpv[j] = xs[tid + j * 256];

            #pragma unroll
            for (int c = 0; c < 8; c++) {
                float4 u = g[2*c], v = g[2*c+1];
                sts128(rb + ((cbase + (uint32_t)(c*16)) ^ msk),
                       pack_h2(u.x,u.y), pack_h2(u.z,u.w), pack_h2(v.x,v.y), pack_h2(v.z,v.w));
            }
            #pragma unroll
            for (int j = 0; j < 8; j++) od[tid + j * 256] = cpv[j];

            if (write_event) {
                int ei = t * 384 + tid;
                out[(size_t)3 * NN * NF + ei] = (float)(ei & (NE - 1));
                if (tid < 128) {
                    int e2 = t * 384 + 256 + tid;
                    out[(size_t)3 * NN * NF + e2] = (float)(e2 & (NE - 1));
                }
            }
        }
        __syncthreads();

        // ---- GEMM1: C1(128x256) = A(128x128) @ W1 ----
        float acc1[4][8][4];
        #pragma unroll
        for (int mf=0; mf<4; mf++)
            #pragma unroll
            for (int nt=0; nt<8; nt++)
                #pragma unroll
                for (int i=0;i<4;i++) acc1[mf][nt][i]=0.f;

        #pragma unroll
        for (int kk = 0; kk < 8; kk++) {
            const uint32_t ksw  = (((uint32_t)(kk*32)) + ahi) ^ amask;
            const uint32_t koff = (((uint32_t)(kk*32)) + bq)  ^ bmsk;
            uint32_t A[4][4];
            #pragma unroll
            for (int mf = 0; mf < 4; mf++)
                ldmx4(A[mf][0],A[mf][1],A[mf][2],A[mf][3], a1Base[mf] + ksw);
            #pragma unroll
            for (int j = 0; j < 4; j++) {
                uint32_t b0,b1,b2,b3;
                ldmx4(b0,b1,b2,b3, b1Ldsm + (uint32_t)j*4096u + koff);
                #pragma unroll
                for (int mf = 0; mf < 4; mf++) {
                    mma16(acc1[mf][2*j],   A[mf][0],A[mf][1],A[mf][2],A[mf][3], b0, b1);
                    mma16(acc1[mf][2*j+1], A[mf][0],A[mf][1],A[mf][2],A[mf][3], b2, b3);
                }
            }
        }

        // ---- Epilogue 1: bias+relu+pack -> sH, keep own slice in regs ----
        uint32_t hA[4][8], hB[4][8];
        #pragma unroll
        for (int mf=0; mf<4; mf++){
            const uint32_t rb0 = sHu + (uint32_t)(64*wm + 16*mf + grp) * 512u;
            const uint32_t rb1 = rb0 + 8u * 512u;
            #pragma unroll
            for (int nt=0; nt<8; nt++){
                const int c0 = nb1 + nt*8 + 2*tig;
                float bz0 = sb1[c0], bz1 = sb1[c0+1];
                uint32_t p01 = pack_h2(fmaxf(acc1[mf][nt][0]+bz0,0.f), fmaxf(acc1[mf][nt][1]+bz1,0.f));
                uint32_t p23 = pack_h2(fmaxf(acc1[mf][nt][2]+bz0,0.f), fmaxf(acc1[mf][nt][3]+bz1,0.f));
                const uint32_t csw = (((uint32_t)(128*wn + nt*16)) ^ (((uint32_t)grp) << 4)) + (uint32_t)(4*tig);
                sts32(rb0 + csw, p01);
                sts32(rb1 + csw, p23);
                hA[mf][nt] = p01; hB[mf][nt] = p23;
            }
        }
        __syncthreads();

        // ---- prefetch next tile's pidx (breaks dependent-load chain of next phase A) ----
        {
            int tn = t + gridDim.x;
            if (tn < NTILES) pi_cur = pidx[(tn << 7) + gr];
        }

        // ---- GEMM2: C2(128x128) = h(128x256) @ W2; own k-slice from registers ----
        float acc2[4][4][4];
        #pragma unroll
        for (int mf=0; mf<4; mf++)
            #pragma unroll
            for (int nt=0; nt<4; nt++)
                #pragma unroll
                for (int i=0;i<4;i++) acc2[mf][nt][i]=0.f;

        #pragma unroll
        for (int s = 0; s < 16; s++) {
            uint32_t A[4][4];
            if ((s >> 2) == wn) {
                const int kkl = s & 3;
                #pragma unroll
                for (int mf = 0; mf < 4; mf++) {
                    A[mf][0] = hA[mf][2*kkl];   A[mf][1] = hB[mf][2*kkl];
                    A[mf][2] = hA[mf][2*kkl+1]; A[mf][3] = hB[mf][2*kkl+1];
                }
            } else {
                const uint32_t ksw = (((uint32_t)(s*32)) + ahi) ^ amask;
                #pragma unroll
                for (int mf = 0; mf < 4; mf++)
                    ldmx4(A[mf][0],A[mf][1],A[mf][2],A[mf][3], a2Base[mf] + ksw);
            }
            const uint32_t koff = (((uint32_t)(s*32)) + bq) ^ bmsk;
            #pragma unroll
            for (int j = 0; j < 2; j++) {
                uint32_t b0,b1,b2,b3;
                ldmx4(b0,b1,b2,b3, b2Ldsm + (uint32_t)j*8192u + koff);
                #pragma unroll
                for (int mf = 0; mf < 4; mf++) {
                    mma16(acc2[mf][2*j],   A[mf][0],A[mf][1],A[mf][2],A[mf][3], b0, b1);
                    mma16(acc2[mf][2*j+1], A[mf][0],A[mf][1],A[mf][2],A[mf][3], b2, b3);
                }
            }
        }

        // ---- Epilogue 2: bias + branch-permuted scatter ----
        const int p  = m0 >> 13;
        const int e0 = m0 & (NE - 1);
        #pragma unroll
        for (int mf=0; mf<4; mf++){
            const int r0 = 64*wm + 16*mf + grp;
            #pragma unroll
            for (int nt=0; nt<4; nt++){
                const int c0 = nb2 + nt*8 + 2*tig;
                const int br = c0 >> 6, fc = c0 & 63;
                const size_t rowbase = (size_t)NN + (size_t)(2*p + br) * NE + (size_t)e0;
                float bz0 = sb2[c0], bz1 = sb2[c0+1];
                float2 v0 = { acc2[mf][nt][0] + bz0, acc2[mf][nt][1] + bz1 };
                float2 v1 = { acc2[mf][nt][2] + bz0, acc2[mf][nt][3] + bz1 };
                *(float2*)(out + (rowbase + r0)     * NF + fc) = v0;
                *(float2*)(out + (rowbase + r0 + 8) * NF + fc) = v1;
            }
        }
        // sync at top of next iteration (after phase A) orders sA/sH reuse correctly
    }
}

extern "C" void kernel_launch(void* const* d_in, const int* in_sizes, int n_in,
                              void* d_out, int out_size)
{
    const float* x   = (const float*)d_in[0];
    const float* gf  = (const float*)d_in[1];
    const float* W1  = (const float*)d_in[2];
    const float* b1  = (const float*)d_in[3];
    const float* W2  = (const float*)d_in[4];
    const float* b2  = (const float*)d_in[5];
    const int*  pidx = (const int*)d_in[6];
    float* out = (float*)d_out;

    int write_event = (out_size >= (3 * NN * NF + 3 * NN)) ? 1 : 0;

    int dev = 0, nsm = 148;
    cudaGetDevice(&dev);
    cudaDeviceGetAttribute(&nsm, cudaDevAttrMultiProcessorCount, dev);
    if (nsm <= 0 || nsm > NTILES) nsm = 148;

    cudaFuncSetAttribute(fused_h16c, cudaFuncAttributeMaxDynamicSharedMemorySize, SMEM_REQ);
    fused_h16c<<<nsm, NTHREADS, SMEM_REQ>>>(x, gf, W1, b1, W2, b2, pidx, out, write_event);
}

// round 6
// speedup vs baseline: 1.0866x; 1.0866x over previous
#include <cuda_runtime.h>
#include <cuda_fp16.h>
#include <cstdint>
#include <cstddef>

#define NE 8192
#define NF 64
#define NH 256
#define NN (128*8192)
#define NTILES 8192
#define NTHREADS 512

// smem byte offsets (all swizzled f16)
#define OFF_SA   0u        // A tile [128][128k] f16, row stride 256B
#define OFF_SH   32768u    // h tile [128][256k] f16, row stride 512B
#define OFF_SW1  98304u    // W1^T  [256n][128k] f16, row stride 256B
#define OFF_SW2  163840u   // W2^T  [128n][256k] f16, row stride 512B
#define OFF_SB1  229376u
#define OFF_SB2  230400u
#define SMEM_REQ 230912

__device__ __forceinline__ uint32_t smem_u32(const void* p){
    uint32_t a;
    asm("{ .reg .u64 t; cvta.to.shared.u64 t, %1; cvt.u32.u64 %0, t; }" : "=r"(a) : "l"(p));
    return a;
}
__device__ __forceinline__ uint32_t pack_h2(float a, float b){
    __half2 h = __floats2half2_rn(a, b);
    return *reinterpret_cast<uint32_t*>(&h);
}
__device__ __forceinline__ void ldmx4(uint32_t& a0, uint32_t& a1, uint32_t& a2, uint32_t& a3, uint32_t addr){
    asm volatile("ldmatrix.sync.aligned.m8n8.x4.shared.b16 {%0,%1,%2,%3}, [%4];"
                 : "=r"(a0), "=r"(a1), "=r"(a2), "=r"(a3) : "r"(addr));
}
__device__ __forceinline__ void sts32(uint32_t addr, uint32_t v){
    asm volatile("st.shared.b32 [%0], %1;" :: "r"(addr), "r"(v) : "memory");
}
__device__ __forceinline__ void sts128(uint32_t addr, uint32_t p0, uint32_t p1, uint32_t p2, uint32_t p3){
    asm volatile("st.shared.v4.b32 [%0], {%1,%2,%3,%4};" :: "r"(addr), "r"(p0), "r"(p1), "r"(p2), "r"(p3) : "memory");
}
__device__ __forceinline__ void mma16(float c[4], uint32_t a0, uint32_t a1, uint32_t a2, uint32_t a3,
                                      uint32_t b0, uint32_t b1){
    asm volatile(
        "mma.sync.aligned.m16n8k16.row.col.f32.f16.f16.f32 "
        "{%0,%1,%2,%3},{%4,%5,%6,%7},{%8,%9},{%0,%1,%2,%3};\n"
        : "+f"(c[0]), "+f"(c[1]), "+f"(c[2]), "+f"(c[3])
        : "r"(a0), "r"(a1), "r"(a2), "r"(a3), "r"(b0), "r"(b1));
}

__global__ void __launch_bounds__(NTHREADS, 1)
fused_h16d(const float* __restrict__ x,  const float* __restrict__ gf,
           const float* __restrict__ W1, const float* __restrict__ b1g,
           const float* __restrict__ W2, const float* __restrict__ b2g,
           const int*   __restrict__ pidx, float* __restrict__ out, int write_event)
{
    extern __shared__ char sm[];
    const int tid  = threadIdx.x;
    const int warp = tid >> 5, lane = tid & 31;
    const int grp = lane >> 2, tig = lane & 3;
    const int wm = warp >> 2, wn = warp & 3;   // 4 x 4 warp grid

    const uint32_t smu = smem_u32(sm);
    const uint32_t sAu = smu + OFF_SA;
    const uint32_t sHu = smu + OFF_SH;
    float* sb1 = (float*)(sm + OFF_SB1);
    float* sb2 = (float*)(sm + OFF_SB2);

    // ---- one-time weight preload (swizzled f16) ----
    for (int i = tid; i < 128 * NH; i += NTHREADS) {
        int k = i >> 8, n = i & 255;
        uint32_t cb = (uint32_t)(2 * k);
        uint32_t off = (uint32_t)n * 256u + ((cb & ~15u) ^ (((uint32_t)n & 7u) << 4)) + (cb & 15u);
        *(half*)(sm + OFF_SW1 + off) = __float2half_rn(W1[i]);
    }
    for (int i = tid; i < NH * 128; i += NTHREADS) {
        int k = i >> 7, n = i & 127;
        uint32_t cb = (uint32_t)(2 * k);
        uint32_t off = (uint32_t)n * 512u + ((cb & ~15u) ^ (((uint32_t)n & 7u) << 4)) + (cb & 15u);
        *(half*)(sm + OFF_SW2 + off) = __float2half_rn(W2[i]);
    }
    if (tid < NH)  sb1[tid] = b1g[tid];
    if (tid < 128) sb2[tid] = b2g[tid];
    __syncthreads();

    // per-thread constants
    const uint32_t amask = ((uint32_t)(lane & 7)) << 4;   // A ldmatrix swizzle
    const uint32_t ahi   = ((uint32_t)(lane >> 4)) << 4;  // A k-half select
    const int lr = lane & 15;

    // B ldmatrix lane mapping
    const uint32_t browSel = (uint32_t)(((lane & 16) >> 1) + (lane & 7));
    const uint32_t bq      = (uint32_t)((lane & 8) << 1);
    const uint32_t bmsk    = ((uint32_t)(lane & 7)) << 4;

    const int nbw = wn * 32;    // warp n-base within each 128-wide half / GEMM2 output
    const uint32_t b2Ldsm = smu + OFF_SW2 + ((uint32_t)nbw + browSel) * 512u;

    uint32_t a1Base[2], a2Base[2];
    #pragma unroll
    for (int mf = 0; mf < 2; mf++) {
        a1Base[mf] = sAu + (uint32_t)(32*wm + 16*mf + lr) * 256u;
        a2Base[mf] = sHu + (uint32_t)(32*wm + 16*mf + lr) * 512u;
    }

    // gather assignment: 4 threads per row
    const int gr = tid >> 2, gq = tid & 3;
    int pi_cur = pidx[(blockIdx.x << 7) + gr];

    // ================= persistent tile loop =================
    for (int t = blockIdx.x; t < NTILES; t += gridDim.x) {
        const int m0 = t << 7;

        // ---- Phase A: gather A (swizzled f16) + identity copy + event ----
        {
            const uint32_t rb  = sAu + (uint32_t)gr * 256u;
            const uint32_t msk = ((uint32_t)(gr & 7)) << 4;
            const float4* src = (gq < 2)
                ? (const float4*)(x  + (size_t)pi_cur * NF + gq * 32)
                : (const float4*)(gf + (size_t)(((unsigned)pi_cur) & (NE-1)) * NF + (gq - 2) * 32);
            const uint32_t cbase = (uint32_t)gq * 64u;

            float4 g[8];
            #pragma unroll
            for (int c = 0; c < 8; c++) g[c] = src[c];

            uint4 cpv[4];
            const uint4* xs = (const uint4*)x + (size_t)t * 2048;
            uint4*       od = (uint4*)out     + (size_t)t * 2048;
            #pragma unroll
            for (int j = 0; j < 4; j++) cpv[j] = xs[tid + j * 512];

            #pragma unroll
            for (int c = 0; c < 4; c++) {
                float4 u = g[2*c], v = g[2*c+1];
                sts128(rb + ((cbase + (uint32_t)(c*16)) ^ msk),
                       pack_h2(u.x,u.y), pack_h2(u.z,u.w), pack_h2(v.x,v.y), pack_h2(v.z,v.w));
            }
            #pragma unroll
            for (int j = 0; j < 4; j++) od[tid + j * 512] = cpv[j];

            if (write_event && tid < 384) {
                int ei = t * 384 + tid;
                out[(size_t)3 * NN * NF + ei] = (float)(ei & (NE - 1));
            }
            int tn = t + gridDim.x;
            if (tn < NTILES) pi_cur = pidx[(tn << 7) + gr];
        }
        __syncthreads();

        // ---- GEMM2 accumulators persist across both hidden halves ----
        float acc2[2][4][4];
        #pragma unroll
        for (int mf=0; mf<2; mf++)
            #pragma unroll
            for (int nt=0; nt<4; nt++)
                #pragma unroll
                for (int i=0;i<4;i++) acc2[mf][nt][i]=0.f;

        #pragma unroll
        for (int hh = 0; hh < 2; hh++) {
            // ---- GEMM1 half: C1h(128x128) = A(128x128) @ W1[:, hh*128:+128) ----
            float acc1[2][4][4];
            #pragma unroll
            for (int mf=0; mf<2; mf++)
                #pragma unroll
                for (int nt=0; nt<4; nt++)
                    #pragma unroll
                    for (int i=0;i<4;i++) acc1[mf][nt][i]=0.f;

            const uint32_t b1LdsmH = smu + OFF_SW1 + ((uint32_t)(hh*128 + nbw) + browSel) * 256u;
            #pragma unroll
            for (int kk = 0; kk < 8; kk++) {
                const uint32_t ksw  = (((uint32_t)(kk*32)) + ahi) ^ amask;
                const uint32_t koff = (((uint32_t)(kk*32)) + bq)  ^ bmsk;
                uint32_t A[2][4];
                #pragma unroll
                for (int mf = 0; mf < 2; mf++)
                    ldmx4(A[mf][0],A[mf][1],A[mf][2],A[mf][3], a1Base[mf] + ksw);
                #pragma unroll
                for (int j = 0; j < 2; j++) {
                    uint32_t b0,b1,b2,b3;
                    ldmx4(b0,b1,b2,b3, b1LdsmH + (uint32_t)j*4096u + koff);
                    #pragma unroll
                    for (int mf = 0; mf < 2; mf++) {
                        mma16(acc1[mf][2*j],   A[mf][0],A[mf][1],A[mf][2],A[mf][3], b0, b1);
                        mma16(acc1[mf][2*j+1], A[mf][0],A[mf][1],A[mf][2],A[mf][3], b2, b3);
                    }
                }
            }

            // ---- Epilogue 1 half: bias+relu+pack -> sH half, keep own slice in regs ----
            uint32_t hA[2][4], hB[2][4];
            #pragma unroll
            for (int mf=0; mf<2; mf++){
                const uint32_t rb0 = sHu + (uint32_t)(32*wm + 16*mf + grp) * 512u;
                const uint32_t rb1 = rb0 + 8u * 512u;
                #pragma unroll
                for (int nt=0; nt<4; nt++){
                    const int c0 = hh*128 + nbw + nt*8 + 2*tig;
                    float bz0 = sb1[c0], bz1 = sb1[c0+1];
                    uint32_t p01 = pack_h2(fmaxf(acc1[mf][nt][0]+bz0,0.f), fmaxf(acc1[mf][nt][1]+bz1,0.f));
                    uint32_t p23 = pack_h2(fmaxf(acc1[mf][nt][2]+bz0,0.f), fmaxf(acc1[mf][nt][3]+bz1,0.f));
                    const uint32_t csw = (((uint32_t)(hh*256 + wn*64 + nt*16)) ^ (((uint32_t)grp) << 4))
                                         + (uint32_t)(4*tig);
                    sts32(rb0 + csw, p01);
                    sts32(rb1 + csw, p23);
                    hA[mf][nt] = p01; hB[mf][nt] = p23;
                }
            }
            __syncthreads();

            // ---- GEMM2 partial: acc2 += h[:, hh*128:+128) @ W2[hh*128:+128, :] ----
            #pragma unroll
            for (int s = 0; s < 8; s++) {
                const int sg = hh*8 + s;      // global k16 step
                uint32_t A[2][4];
                if ((s >> 1) == wn) {
                    const int kkl = s & 1;
                    #pragma unroll
                    for (int mf = 0; mf < 2; mf++) {
                        A[mf][0] = hA[mf][2*kkl];   A[mf][1] = hB[mf][2*kkl];
                        A[mf][2] = hA[mf][2*kkl+1]; A[mf][3] = hB[mf][2*kkl+1];
                    }
                } else {
                    const uint32_t ksw = (((uint32_t)(sg*32)) + ahi) ^ amask;
                    #pragma unroll
                    for (int mf = 0; mf < 2; mf++)
                        ldmx4(A[mf][0],A[mf][1],A[mf][2],A[mf][3], a2Base[mf] + ksw);
                }
                const uint32_t koff = (((uint32_t)(sg*32)) + bq) ^ bmsk;
                #pragma unroll
                for (int j = 0; j < 2; j++) {
                    uint32_t b0,b1,b2,b3;
                    ldmx4(b0,b1,b2,b3, b2Ldsm + (uint32_t)j*8192u + koff);
                    #pragma unroll
                    for (int mf = 0; mf < 2; mf++) {
                        mma16(acc2[mf][2*j],   A[mf][0],A[mf][1],A[mf][2],A[mf][3], b0, b1);
                        mma16(acc2[mf][2*j+1], A[mf][0],A[mf][1],A[mf][2],A[mf][3], b2, b3);
                    }
                }
            }
        }

        // ---- Epilogue 2: bias + branch-permuted scatter ----
        const int p  = m0 >> 13;
        const int e0 = m0 & (NE - 1);
        #pragma unroll
        for (int mf=0; mf<2; mf++){
            const int r0 = 32*wm + 16*mf + grp;
            #pragma unroll
            for (int nt=0; nt<4; nt++){
                const int c0 = nbw + nt*8 + 2*tig;
                const int br = c0 >> 6, fc = c0 & 63;
                const size_t rowbase = (size_t)NN + (size_t)(2*p + br) * NE + (size_t)e0;
                float bz0 = sb2[c0], bz1 = sb2[c0+1];
                float2 v0 = { acc2[mf][nt][0] + bz0, acc2[mf][nt][1] + bz1 };
                float2 v1 = { acc2[mf][nt][2] + bz0, acc2[mf][nt][3] + bz1 };
                *(float2*)(out + (rowbase + r0)     * NF + fc) = v0;
                *(float2*)(out + (rowbase + r0 + 8) * NF + fc) = v1;
            }
        }
        // top-of-loop barrier (BAR1 of next tile) orders sA/sH reuse
    }
}

extern "C" void kernel_launch(void* const* d_in, const int* in_sizes, int n_in,
                              void* d_out, int out_size)
{
    const float* x   = (const float*)d_in[0];
    const float* gf  = (const float*)d_in[1];
    const float* W1  = (const float*)d_in[2];
    const float* b1  = (const float*)d_in[3];
    const float* W2  = (const float*)d_in[4];
    const float* b2  = (const float*)d_in[5];
    const int*  pidx = (const int*)d_in[6];
    float* out = (float*)d_out;

    int write_event = (out_size >= (3 * NN * NF + 3 * NN)) ? 1 : 0;

    int dev = 0, nsm = 148;
    cudaGetDevice(&dev);
    cudaDeviceGetAttribute(&nsm, cudaDevAttrMultiProcessorCount, dev);
    if (nsm <= 0 || nsm > NTILES) nsm = 148;

    cudaFuncSetAttribute(fused_h16d, cudaFuncAttributeMaxDynamicSharedMemorySize, SMEM_REQ);
    fused_h16d<<<nsm, NTHREADS, SMEM_REQ>>>(x, gf, W1, b1, W2, b2, pidx, out, write_event);
}